// round 1
// baseline (speedup 1.0000x reference)
#include <cuda_runtime.h>

#define BDIM 2
#define C 256
#define H 96
#define W 96
#define HW (H*W)          // 9216
#define MPIX (BDIM*HW)    // 18432
#define OC 256
#define NTAP 9
#define KDIM (C*NTAP)     // 2304
#define HP 98

// -------- scratch (static device globals; no allocations) --------
__device__ float        g_X[(size_t)KDIM * MPIX];   // [j][m], j = k*256 + c  (~170MB)
__device__ float        g_Wt[(size_t)KDIM * OC];    // [j][o]
__device__ unsigned int g_qpack[NTAP * MPIX];       // packed corner coords
__device__ float4       g_w4[NTAP * MPIX];          // bilinear weights (lt,rb,lb,rt)

// ================= Kernel 0: weight transpose =================
// g_Wt[(k*C+c)*OC + o] = w_conv[(o*C + c)*9 + k]
__global__ void __launch_bounds__(256) wt_kernel(const float* __restrict__ wc)
{
    int c = blockIdx.x;      // 0..255
    int o = threadIdx.x;     // 0..255
    float v[9];
#pragma unroll
    for (int k = 0; k < 9; k++) v[k] = __ldg(&wc[((size_t)o*C + c)*9 + k]);
#pragma unroll
    for (int k = 0; k < 9; k++) g_Wt[(size_t)(k*C + c)*OC + o] = v[k];
}

// ================= Kernel 1: offset conv + position/weight precompute =================
// block: 256 threads = 64 pixel-lanes (tx) x 4 channel-splits (ty); 2 pixels per lane.
__global__ void __launch_bounds__(256) offset_kernel(
    const float* __restrict__ x,  const float* __restrict__ w_p,
    const float* __restrict__ b_p, const float* __restrict__ w_ad,
    const float* __restrict__ b_ad)
{
    const int tid = threadIdx.x;
    const int tx  = tid & 63;
    const int ty  = tid >> 6;                // split 0..3 (64 channels each)
    const int mA  = blockIdx.x * 128 + tx;
    const int mB  = mA + 64;

    __shared__ float wbuf[32][192];          // [s*8+cc][oc*9+t]  24KB
    __shared__ float red[4][21][64];         // reduction buffer   21.5KB

    const int bA = mA / HW, hwA = mA % HW, hA = hwA / W, wA = hwA % W;
    const int bB = mB / HW, hwB = mB % HW, hB = hwB / W, wB = hwB % W;

    float acc[2][21];
#pragma unroll
    for (int p = 0; p < 2; p++)
#pragma unroll
        for (int oc = 0; oc < 21; oc++) acc[p][oc] = 0.f;

    const float* xA = x + (size_t)bA * C * HW;
    const float* xB = x + (size_t)bB * C * HW;

#pragma unroll 1
    for (int ch = 0; ch < 8; ch++) {         // 8 chunks of 8 channels per split
        __syncthreads();
        // cooperative weight stage: row = s*8+cc -> channel c = s*64 + ch*8 + cc
        for (int idx = tid; idx < 32 * 189; idx += 256) {
            int row = idx / 189, e = idx % 189;
            int oc = e / 9, t = e % 9;
            int c = (row >> 3) * 64 + ch * 8 + (row & 7);
            float wv = (oc < 18) ? __ldg(&w_p[((size_t)oc*C + c)*9 + t])
                                 : __ldg(&w_ad[((size_t)(oc-18)*C + c)*9 + t]);
            wbuf[row][e] = wv;
        }
        __syncthreads();
#pragma unroll 1
        for (int cc = 0; cc < 8; cc++) {
            const int c = ty * 64 + ch * 8 + cc;
            const float* plA = xA + (size_t)c * HW;
            const float* plB = xB + (size_t)c * HW;
            float vA[9], vB[9];
#pragma unroll
            for (int t = 0; t < 9; t++) {
                int dh = t / 3 - 1, dw = t % 3 - 1;
                int h1 = hA + dh, w1 = wA + dw;
                vA[t] = (h1 >= 0 && h1 < H && w1 >= 0 && w1 < W) ? __ldg(&plA[h1*W + w1]) : 0.f;
                int h2 = hB + dh, w2 = wB + dw;
                vB[t] = (h2 >= 0 && h2 < H && w2 >= 0 && w2 < W) ? __ldg(&plB[h2*W + w2]) : 0.f;
            }
            const float* wr = &wbuf[ty * 8 + cc][0];
#pragma unroll
            for (int oc = 0; oc < 21; oc++) {
#pragma unroll
                for (int t = 0; t < 9; t++) {
                    float wv = wr[oc*9 + t];
                    acc[0][oc] += vA[t] * wv;
                    acc[1][oc] += vB[t] * wv;
                }
            }
        }
    }

#pragma unroll 1
    for (int p = 0; p < 2; p++) {
        __syncthreads();
#pragma unroll
        for (int oc = 0; oc < 21; oc++) red[ty][oc][tx] = acc[p][oc];
        __syncthreads();
        if (ty == 0) {
            const int m = (p == 0) ? mA : mB;
            const int h = (p == 0) ? hA : hB;
            const int w = (p == 0) ? wA : wB;
            float a[21];
#pragma unroll
            for (int oc = 0; oc < 21; oc++)
                a[oc] = red[0][oc][tx] + red[1][oc][tx] + red[2][oc][tx] + red[3][oc][tx];
#pragma unroll
            for (int k = 0; k < 9; k++) {
                float pnx = (float)(k / 3) - 1.f;
                float pny = (float)(k % 3) - 1.f;
                float z   = a[18 + (k % 3)] + __ldg(&b_ad[k % 3]);
                float sig = 1.f / (1.f + expf(-z));
                float ad  = 2.f * (1.f - sig);
                float px = (float)(h + 1) + pnx + a[k]     + __ldg(&b_p[k])     + ad * pnx;
                float py = (float)(w + 1) + pny + a[9 + k] + __ldg(&b_p[9 + k]) + ad * pny;
                float fx = floorf(px), fy = floorf(py);
                int iltx = (int)fx, ilty = (int)fy;
                int ltx = min(max(iltx,     0), HP - 1), lty = min(max(ilty,     0), HP - 1);
                int rbx = min(max(iltx + 1, 0), HP - 1), rby = min(max(ilty + 1, 0), HP - 1);
                // mask (from ORIGINAL p), then floor-replace, then clip
                bool mx = (px < 1.f) || (px > (float)(HP - 2));
                bool my = (py < 1.f) || (py > (float)(HP - 2));
                if (mx) px = fx;
                if (my) py = fy;
                px = fminf(fmaxf(px, 0.f), (float)(HP - 1));
                py = fminf(fmaxf(py, 0.f), (float)(HP - 1));
                float dxl = 1.f + ((float)ltx - px);
                float dyl = 1.f + ((float)lty - py);
                float dxr = 1.f - ((float)rbx - px);
                float dyr = 1.f - ((float)rby - py);
                g_qpack[k*MPIX + m] = (unsigned)ltx | ((unsigned)lty << 8)
                                    | ((unsigned)rbx << 16) | ((unsigned)rby << 24);
                g_w4[k*MPIX + m] = make_float4(dxl*dyl, dxr*dyr, dxl*dyr, dxr*dyl);
            }
        }
    }
}

// ================= Kernel 2: bilinear gather -> X matrix =================
__global__ void __launch_bounds__(256) sample_kernel(const float* __restrict__ x)
{
    const int m  = blockIdx.x * 256 + threadIdx.x;
    const int k  = blockIdx.z;
    const int c0 = blockIdx.y * 8;
    const unsigned qp = g_qpack[k*MPIX + m];
    const float4 g = g_w4[k*MPIX + m];
    const int ltx = qp & 255, lty = (qp >> 8) & 255, rbx = (qp >> 16) & 255, rby = (qp >> 24) & 255;
    const bool ax  = (ltx >= 1) && (ltx <= 96);
    const bool axr = (rbx >= 1) && (rbx <= 96);
    const bool ay  = (lty >= 1) && (lty <= 96);
    const bool ayr = (rby >= 1) && (rby <= 96);
    const float glt = (ax  && ay ) ? g.x : 0.f;
    const float grb = (axr && ayr) ? g.y : 0.f;
    const float glb = (ax  && ayr) ? g.z : 0.f;
    const float grt = (axr && ay ) ? g.w : 0.f;
    const int oLT = (ax  && ay ) ? (ltx - 1) * W + (lty - 1) : 0;
    const int oRB = (axr && ayr) ? (rbx - 1) * W + (rby - 1) : 0;
    const int oLB = (ax  && ayr) ? (ltx - 1) * W + (rby - 1) : 0;
    const int oRT = (axr && ay ) ? (rbx - 1) * W + (lty - 1) : 0;
    const int b = m / HW;
    const float* xb = x + (size_t)(b * C + c0) * HW;
    float* Xp = &g_X[(size_t)(k * C + c0) * MPIX + m];
#pragma unroll
    for (int cc = 0; cc < 8; cc++) {
        const float* pl = xb + (size_t)cc * HW;
        float v = glt * __ldg(&pl[oLT]) + grb * __ldg(&pl[oRB])
                + glb * __ldg(&pl[oLB]) + grt * __ldg(&pl[oRT]);
        Xp[(size_t)cc * MPIX] = v;
    }
}

// ================= Kernel 3: SGEMM with packed f32x2 FFMA2 =================
#define BM 128
#define BN 128
#define BK 16

__device__ __forceinline__ unsigned long long fma2(
    unsigned long long a, unsigned long long b, unsigned long long c)
{
    unsigned long long d;
    asm("fma.rn.f32x2 %0, %1, %2, %3;" : "=l"(d) : "l"(a), "l"(b), "l"(c));
    return d;
}

__global__ void __launch_bounds__(256, 2) gemm_kernel(float* __restrict__ out)
{
    __shared__ float Wsd[BK][2 * BN];   // W tile, each value duplicated (for f32x2 A-operand)
    __shared__ float Xs[BK][BM];

    const int tid = threadIdx.x;
    const int m0 = blockIdx.x * BM;
    const int o0 = blockIdx.y * BN;
    const int lr = tid >> 5;            // load row 0..7 (and +8)
    const int lc = (tid & 31) << 2;     // load col (float4)
    const int ty = tid >> 4;            // 0..15 -> o frag
    const int txf = tid & 15;           // 0..15 -> m frag

    unsigned long long acc[8][4];
#pragma unroll
    for (int i = 0; i < 8; i++)
#pragma unroll
        for (int j = 0; j < 4; j++) acc[i][j] = 0ull;

    const float* Wg = &g_Wt[(size_t)lr * OC + o0 + lc];
    const float* Xg = &g_X[(size_t)lr * MPIX + m0 + lc];

    for (int j0 = 0; j0 < KDIM; j0 += BK) {
        float4 a0 = *(const float4*)(Wg + (size_t)j0 * OC);
        float4 a1 = *(const float4*)(Wg + (size_t)(j0 + 8) * OC);
        float4 b0 = *(const float4*)(Xg + (size_t)j0 * MPIX);
        float4 b1 = *(const float4*)(Xg + (size_t)(j0 + 8) * MPIX);
        __syncthreads();
        *(float4*)&Wsd[lr][2*lc]       = make_float4(a0.x, a0.x, a0.y, a0.y);
        *(float4*)&Wsd[lr][2*lc + 4]   = make_float4(a0.z, a0.z, a0.w, a0.w);
        *(float4*)&Wsd[lr+8][2*lc]     = make_float4(a1.x, a1.x, a1.y, a1.y);
        *(float4*)&Wsd[lr+8][2*lc + 4] = make_float4(a1.z, a1.z, a1.w, a1.w);
        *(float4*)&Xs[lr][lc]    = b0;
        *(float4*)&Xs[lr+8][lc]  = b1;
        __syncthreads();
#pragma unroll
        for (int kk = 0; kk < BK; kk++) {
            unsigned long long a2[8], b2[4];
            const unsigned long long* wr = (const unsigned long long*)&Wsd[kk][ty * 16];
            const unsigned long long* xr = (const unsigned long long*)&Xs[kk][txf * 8];
#pragma unroll
            for (int i = 0; i < 8; i++) a2[i] = wr[i];
#pragma unroll
            for (int j = 0; j < 4; j++) b2[j] = xr[j];
#pragma unroll
            for (int i = 0; i < 8; i++)
#pragma unroll
                for (int j = 0; j < 4; j++)
                    acc[i][j] = fma2(a2[i], b2[j], acc[i][j]);
        }
    }

    // epilogue: out[(b*OC + o)*HW + hw]
    const int b   = m0 / HW;            // BM divides HW -> no straddle
    const int hw0 = (m0 % HW) + txf * 8;
#pragma unroll
    for (int i = 0; i < 8; i++) {
        int o = o0 + ty * 8 + i;
        float* orow = out + (size_t)(b * OC + o) * HW + hw0;
#pragma unroll
        for (int j = 0; j < 4; j++) {
            unsigned long long v = acc[i][j];
            float2 f;
            f.x = __uint_as_float((unsigned)(v & 0xffffffffull));
            f.y = __uint_as_float((unsigned)(v >> 32));
            *(float2*)(orow + j * 2) = f;
        }
    }
}

// ================= launch =================
extern "C" void kernel_launch(void* const* d_in, const int* in_sizes, int n_in,
                              void* d_out, int out_size)
{
    const float* x      = (const float*)d_in[0];
    const float* w_p    = (const float*)d_in[1];
    const float* b_p    = (const float*)d_in[2];
    const float* w_ad   = (const float*)d_in[3];
    const float* b_ad   = (const float*)d_in[4];
    const float* w_conv = (const float*)d_in[5];
    float* out = (float*)d_out;

    wt_kernel<<<C, 256>>>(w_conv);
    offset_kernel<<<MPIX / 128, 256>>>(x, w_p, b_p, w_ad, b_ad);
    sample_kernel<<<dim3(MPIX / 256, C / 8, NTAP), 256>>>(x);
    gemm_kernel<<<dim3(MPIX / BM, OC / BN), 256>>>(out);
}

// round 2
// speedup vs baseline: 1.0576x; 1.0576x over previous
#include <cuda_runtime.h>

#define BDIM 2
#define C 256
#define H 96
#define W 96
#define HW (H*W)          // 9216
#define MPIX (BDIM*HW)    // 18432
#define OC 256
#define NTAP 9
#define KDIM (C*NTAP)     // 2304
#define HP 98

// -------- scratch (static device globals; no allocations) --------
__device__ float        g_X[(size_t)KDIM * MPIX];   // [j][m], j = k*256 + c  (~170MB)
__device__ float        g_Wt[(size_t)KDIM * OC];    // [j][o]
__device__ unsigned int g_qpack[NTAP * MPIX];       // packed corner coords
__device__ float4       g_w4[NTAP * MPIX];          // bilinear weights (lt,rb,lb,rt)

// ================= Kernel 0: weight transpose =================
__global__ void __launch_bounds__(256) wt_kernel(const float* __restrict__ wc)
{
    int c = blockIdx.x;
    int o = threadIdx.x;
    float v[9];
#pragma unroll
    for (int k = 0; k < 9; k++) v[k] = __ldg(&wc[((size_t)o*C + c)*9 + k]);
#pragma unroll
    for (int k = 0; k < 9; k++) g_Wt[(size_t)(k*C + c)*OC + o] = v[k];
}

// ================= Kernel 1: offset conv + position/weight precompute =================
__global__ void __launch_bounds__(256) offset_kernel(
    const float* __restrict__ x,  const float* __restrict__ w_p,
    const float* __restrict__ b_p, const float* __restrict__ w_ad,
    const float* __restrict__ b_ad)
{
    const int tid = threadIdx.x;
    const int tx  = tid & 63;
    const int ty  = tid >> 6;
    const int mA  = blockIdx.x * 128 + tx;
    const int mB  = mA + 64;

    __shared__ float wbuf[32][192];
    __shared__ float red[4][21][64];

    const int bA = mA / HW, hwA = mA % HW, hA = hwA / W, wA = hwA % W;
    const int bB = mB / HW, hwB = mB % HW, hB = hwB / W, wB = hwB % W;

    float acc[2][21];
#pragma unroll
    for (int p = 0; p < 2; p++)
#pragma unroll
        for (int oc = 0; oc < 21; oc++) acc[p][oc] = 0.f;

    const float* xA = x + (size_t)bA * C * HW;
    const float* xB = x + (size_t)bB * C * HW;

#pragma unroll 1
    for (int ch = 0; ch < 8; ch++) {
        __syncthreads();
        for (int idx = tid; idx < 32 * 189; idx += 256) {
            int row = idx / 189, e = idx % 189;
            int oc = e / 9, t = e % 9;
            int c = (row >> 3) * 64 + ch * 8 + (row & 7);
            float wv = (oc < 18) ? __ldg(&w_p[((size_t)oc*C + c)*9 + t])
                                 : __ldg(&w_ad[((size_t)(oc-18)*C + c)*9 + t]);
            wbuf[row][e] = wv;
        }
        __syncthreads();
#pragma unroll 1
        for (int cc = 0; cc < 8; cc++) {
            const int c = ty * 64 + ch * 8 + cc;
            const float* plA = xA + (size_t)c * HW;
            const float* plB = xB + (size_t)c * HW;
            float vA[9], vB[9];
#pragma unroll
            for (int t = 0; t < 9; t++) {
                int dh = t / 3 - 1, dw = t % 3 - 1;
                int h1 = hA + dh, w1 = wA + dw;
                vA[t] = (h1 >= 0 && h1 < H && w1 >= 0 && w1 < W) ? __ldg(&plA[h1*W + w1]) : 0.f;
                int h2 = hB + dh, w2 = wB + dw;
                vB[t] = (h2 >= 0 && h2 < H && w2 >= 0 && w2 < W) ? __ldg(&plB[h2*W + w2]) : 0.f;
            }
            const float* wr = &wbuf[ty * 8 + cc][0];
#pragma unroll
            for (int oc = 0; oc < 21; oc++) {
#pragma unroll
                for (int t = 0; t < 9; t++) {
                    float wv = wr[oc*9 + t];
                    acc[0][oc] += vA[t] * wv;
                    acc[1][oc] += vB[t] * wv;
                }
            }
        }
    }

#pragma unroll 1
    for (int p = 0; p < 2; p++) {
        __syncthreads();
#pragma unroll
        for (int oc = 0; oc < 21; oc++) red[ty][oc][tx] = acc[p][oc];
        __syncthreads();
        if (ty == 0) {
            const int m = (p == 0) ? mA : mB;
            const int h = (p == 0) ? hA : hB;
            const int w = (p == 0) ? wA : wB;
            float a[21];
#pragma unroll
            for (int oc = 0; oc < 21; oc++)
                a[oc] = red[0][oc][tx] + red[1][oc][tx] + red[2][oc][tx] + red[3][oc][tx];
#pragma unroll
            for (int k = 0; k < 9; k++) {
                float pnx = (float)(k / 3) - 1.f;
                float pny = (float)(k % 3) - 1.f;
                float z   = a[18 + (k % 3)] + __ldg(&b_ad[k % 3]);
                float sig = 1.f / (1.f + expf(-z));
                float ad  = 2.f * (1.f - sig);
                float px = (float)(h + 1) + pnx + a[k]     + __ldg(&b_p[k])     + ad * pnx;
                float py = (float)(w + 1) + pny + a[9 + k] + __ldg(&b_p[9 + k]) + ad * pny;
                float fx = floorf(px), fy = floorf(py);
                int iltx = (int)fx, ilty = (int)fy;
                int ltx = min(max(iltx,     0), HP - 1), lty = min(max(ilty,     0), HP - 1);
                int rbx = min(max(iltx + 1, 0), HP - 1), rby = min(max(ilty + 1, 0), HP - 1);
                bool mx = (px < 1.f) || (px > (float)(HP - 2));
                bool my = (py < 1.f) || (py > (float)(HP - 2));
                if (mx) px = fx;
                if (my) py = fy;
                px = fminf(fmaxf(px, 0.f), (float)(HP - 1));
                py = fminf(fmaxf(py, 0.f), (float)(HP - 1));
                float dxl = 1.f + ((float)ltx - px);
                float dyl = 1.f + ((float)lty - py);
                float dxr = 1.f - ((float)rbx - px);
                float dyr = 1.f - ((float)rby - py);
                g_qpack[k*MPIX + m] = (unsigned)ltx | ((unsigned)lty << 8)
                                    | ((unsigned)rbx << 16) | ((unsigned)rby << 24);
                g_w4[k*MPIX + m] = make_float4(dxl*dyl, dxr*dyr, dxl*dyr, dxr*dyl);
            }
        }
    }
}

// ================= Kernel 2: bilinear gather -> X matrix =================
__global__ void __launch_bounds__(256) sample_kernel(const float* __restrict__ x)
{
    const int m  = blockIdx.x * 256 + threadIdx.x;
    const int k  = blockIdx.z;
    const int c0 = blockIdx.y * 8;
    const unsigned qp = g_qpack[k*MPIX + m];
    const float4 g = g_w4[k*MPIX + m];
    const int ltx = qp & 255, lty = (qp >> 8) & 255, rbx = (qp >> 16) & 255, rby = (qp >> 24) & 255;
    const bool ax  = (ltx >= 1) && (ltx <= 96);
    const bool axr = (rbx >= 1) && (rbx <= 96);
    const bool ay  = (lty >= 1) && (lty <= 96);
    const bool ayr = (rby >= 1) && (rby <= 96);
    const float glt = (ax  && ay ) ? g.x : 0.f;
    const float grb = (axr && ayr) ? g.y : 0.f;
    const float glb = (ax  && ayr) ? g.z : 0.f;
    const float grt = (axr && ay ) ? g.w : 0.f;
    const int oLT = (ax  && ay ) ? (ltx - 1) * W + (lty - 1) : 0;
    const int oRB = (axr && ayr) ? (rbx - 1) * W + (rby - 1) : 0;
    const int oLB = (ax  && ayr) ? (ltx - 1) * W + (rby - 1) : 0;
    const int oRT = (axr && ay ) ? (rbx - 1) * W + (lty - 1) : 0;
    const int b = m / HW;
    const float* xb = x + (size_t)(b * C + c0) * HW;
    float* Xp = &g_X[(size_t)(k * C + c0) * MPIX + m];
#pragma unroll
    for (int cc = 0; cc < 8; cc++) {
        const float* pl = xb + (size_t)cc * HW;
        float v = glt * __ldg(&pl[oLT]) + grb * __ldg(&pl[oRB])
                + glb * __ldg(&pl[oLB]) + grt * __ldg(&pl[oRT]);
        Xp[(size_t)cc * MPIX] = v;
    }
}

// ================= Kernel 3: SGEMM, f32x2 FFMA2, conflict-free smem, double-buffered =================
#define BM 128
#define BN 128
#define BK 16
#define NTILE (KDIM / BK)   // 144

__device__ __forceinline__ unsigned long long fma2(
    unsigned long long a, unsigned long long b, unsigned long long c)
{
    unsigned long long d;
    asm("fma.rn.f32x2 %0, %1, %2, %3;" : "=l"(d) : "l"(a), "l"(b), "l"(c));
    return d;
}

__global__ void __launch_bounds__(256, 2) gemm_kernel(float* __restrict__ out)
{
    // W tile duplicated (each value twice, for f32x2 broadcast operand): [BK][256]
    // X tile permuted: value m_local=q stored at float index ((q%8)/2)*32 + (q/8)*2 + (q%2)
    //   -> thread txf reads its 4 float2 at byte j*128 + txf*8 (conflict-free, 1 wavefront)
    __shared__ float Wsd[2][BK][2 * BN];   // 2 x 16KB
    __shared__ float Xs [2][BK][BM];       // 2 x 8KB

    const int tid = threadIdx.x;
    const int m0 = blockIdx.x * BM;
    const int o0 = blockIdx.y * BN;
    const int lr = tid >> 5;            // load row 0..7 (and +8)
    const int lc = (tid & 31) << 2;     // load col (float4), 0..124
    const int ty = tid >> 4;            // 0..15 -> o frag
    const int txf = tid & 15;           // 0..15 -> m frag

    // Xs store permutation for this thread's float4 (q = lc..lc+3)
    const int j0x = (lc & 7) >> 1;          // 0 or 2
    const int t2  = (lc >> 3) << 1;         // (lc/8)*2

    unsigned long long acc[8][4];
#pragma unroll
    for (int i = 0; i < 8; i++)
#pragma unroll
        for (int j = 0; j < 4; j++) acc[i][j] = 0ull;

    const float* Wg = &g_Wt[(size_t)lr * OC + o0 + lc];
    const float* Xg = &g_X[(size_t)lr * MPIX + m0 + lc];

    // ---- prologue: tile 0 ----
    float4 a0 = *(const float4*)(Wg);
    float4 a1 = *(const float4*)(Wg + (size_t)8 * OC);
    float4 b0 = *(const float4*)(Xg);
    float4 b1 = *(const float4*)(Xg + (size_t)8 * MPIX);
    {
        *(float4*)&Wsd[0][lr][2*lc]       = make_float4(a0.x, a0.x, a0.y, a0.y);
        *(float4*)&Wsd[0][lr][2*lc + 4]   = make_float4(a0.z, a0.z, a0.w, a0.w);
        *(float4*)&Wsd[0][lr+8][2*lc]     = make_float4(a1.x, a1.x, a1.y, a1.y);
        *(float4*)&Wsd[0][lr+8][2*lc + 4] = make_float4(a1.z, a1.z, a1.w, a1.w);
        *(float2*)&Xs[0][lr][j0x*32 + t2]       = make_float2(b0.x, b0.y);
        *(float2*)&Xs[0][lr][(j0x+1)*32 + t2]   = make_float2(b0.z, b0.w);
        *(float2*)&Xs[0][lr+8][j0x*32 + t2]     = make_float2(b1.x, b1.y);
        *(float2*)&Xs[0][lr+8][(j0x+1)*32 + t2] = make_float2(b1.z, b1.w);
    }
    __syncthreads();

    int buf = 0;
#pragma unroll 1
    for (int t = 0; t < NTILE; t++) {
        // prefetch next tile from global
        if (t + 1 < NTILE) {
            size_t j0 = (size_t)(t + 1) * BK;
            a0 = *(const float4*)(Wg + j0 * OC);
            a1 = *(const float4*)(Wg + (j0 + 8) * OC);
            b0 = *(const float4*)(Xg + j0 * MPIX);
            b1 = *(const float4*)(Xg + (j0 + 8) * MPIX);
        }
        // compute on current buffer
#pragma unroll
        for (int kk = 0; kk < BK; kk++) {
            const float4* wr = (const float4*)&Wsd[buf][kk][ty * 16];
            const unsigned long long* xr = (const unsigned long long*)&Xs[buf][kk][0];
            float4 wv0 = wr[0], wv1 = wr[1], wv2 = wr[2], wv3 = wr[3];
            unsigned long long a2[8], b2[4];
            a2[0] = ((const unsigned long long*)&wv0)[0];
            a2[1] = ((const unsigned long long*)&wv0)[1];
            a2[2] = ((const unsigned long long*)&wv1)[0];
            a2[3] = ((const unsigned long long*)&wv1)[1];
            a2[4] = ((const unsigned long long*)&wv2)[0];
            a2[5] = ((const unsigned long long*)&wv2)[1];
            a2[6] = ((const unsigned long long*)&wv3)[0];
            a2[7] = ((const unsigned long long*)&wv3)[1];
#pragma unroll
            for (int j = 0; j < 4; j++) b2[j] = xr[j * 16 + txf];
#pragma unroll
            for (int i = 0; i < 8; i++)
#pragma unroll
                for (int j = 0; j < 4; j++)
                    acc[i][j] = fma2(a2[i], b2[j], acc[i][j]);
        }
        // stage next tile into the other buffer
        if (t + 1 < NTILE) {
            int nb = buf ^ 1;
            *(float4*)&Wsd[nb][lr][2*lc]       = make_float4(a0.x, a0.x, a0.y, a0.y);
            *(float4*)&Wsd[nb][lr][2*lc + 4]   = make_float4(a0.z, a0.z, a0.w, a0.w);
            *(float4*)&Wsd[nb][lr+8][2*lc]     = make_float4(a1.x, a1.x, a1.y, a1.y);
            *(float4*)&Wsd[nb][lr+8][2*lc + 4] = make_float4(a1.z, a1.z, a1.w, a1.w);
            *(float2*)&Xs[nb][lr][j0x*32 + t2]       = make_float2(b0.x, b0.y);
            *(float2*)&Xs[nb][lr][(j0x+1)*32 + t2]   = make_float2(b0.z, b0.w);
            *(float2*)&Xs[nb][lr+8][j0x*32 + t2]     = make_float2(b1.x, b1.y);
            *(float2*)&Xs[nb][lr+8][(j0x+1)*32 + t2] = make_float2(b1.z, b1.w);
            __syncthreads();
            buf = nb;
        }
    }

    // epilogue: out[(b*OC + o)*HW + hw]; acc[i][j] -> m = m0 + txf*8 + 2j + {0,1}
    const int b   = m0 / HW;            // BM divides HW -> no straddle
    const int hw0 = (m0 % HW) + txf * 8;
#pragma unroll
    for (int i = 0; i < 8; i++) {
        int o = o0 + ty * 8 + i;
        float* orow = out + (size_t)(b * OC + o) * HW + hw0;
#pragma unroll
        for (int j = 0; j < 4; j++) {
            unsigned long long v = acc[i][j];
            float2 f;
            f.x = __uint_as_float((unsigned)(v & 0xffffffffull));
            f.y = __uint_as_float((unsigned)(v >> 32));
            *(float2*)(orow + j * 2) = f;
        }
    }
}

// ================= launch =================
extern "C" void kernel_launch(void* const* d_in, const int* in_sizes, int n_in,
                              void* d_out, int out_size)
{
    const float* x      = (const float*)d_in[0];
    const float* w_p    = (const float*)d_in[1];
    const float* b_p    = (const float*)d_in[2];
    const float* w_ad   = (const float*)d_in[3];
    const float* b_ad   = (const float*)d_in[4];
    const float* w_conv = (const float*)d_in[5];
    float* out = (float*)d_out;

    wt_kernel<<<C, 256>>>(w_conv);
    offset_kernel<<<MPIX / 128, 256>>>(x, w_p, b_p, w_ad, b_ad);
    sample_kernel<<<dim3(MPIX / 256, C / 8, NTAP), 256>>>(x);
    gemm_kernel<<<dim3(MPIX / BM, OC / BN), 256>>>(out);
}

// round 4
// speedup vs baseline: 1.9248x; 1.8200x over previous
#include <cuda_runtime.h>
#include <cuda_bf16.h>
#include <cstdint>

#define BDIM 2
#define C 256
#define H 96
#define W 96
#define HW (H*W)          // 9216
#define MPIX (BDIM*HW)    // 18432
#define OC 256
#define NTAP 9
#define KD3 (NTAP*C*3)    // 6912 (K expanded 3x for split-bf16)
#define HP 98

// -------- scratch (static device globals; no allocations) --------
__device__ __align__(128) __nv_bfloat16 g_Xb[(size_t)MPIX * KD3]; // [m][j3] ~255MB
__device__ __align__(128) __nv_bfloat16 g_Wb[(size_t)OC * KD3];   // [o][j3] ~3.5MB
__device__ unsigned int g_qpack[NTAP * MPIX];
__device__ float4       g_w4[NTAP * MPIX];

// ---------------- PTX helpers (base ISA only, no sm_103a features) ----------------
__device__ __forceinline__ uint32_t smem_u32(const void* p) {
    uint32_t a;
    asm("{ .reg .u64 t; cvta.to.shared.u64 t, %1; cvt.u32.u64 %0, t; }" : "=r"(a) : "l"(p));
    return a;
}
__device__ __forceinline__ void cp16(uint32_t s, const void* g) {
    asm volatile("cp.async.cg.shared.global [%0], [%1], 16;" :: "r"(s), "l"(g));
}
__device__ __forceinline__ void cp_commit() {
    asm volatile("cp.async.commit_group;" ::: "memory");
}
template <int N> __device__ __forceinline__ void cp_wait() {
    asm volatile("cp.async.wait_group %0;" :: "n"(N) : "memory");
}
__device__ __forceinline__ void ldsm_x4(uint32_t* r, uint32_t addr) {
    asm volatile("ldmatrix.sync.aligned.m8n8.x4.shared.b16 {%0,%1,%2,%3}, [%4];"
        : "=r"(r[0]), "=r"(r[1]), "=r"(r[2]), "=r"(r[3]) : "r"(addr));
}
__device__ __forceinline__ void mma16816(float* d, const uint32_t* a, const uint32_t* b) {
    asm volatile("mma.sync.aligned.m16n8k16.row.col.f32.bf16.bf16.f32 "
        "{%0,%1,%2,%3}, {%4,%5,%6,%7}, {%8,%9}, {%0,%1,%2,%3};"
        : "+f"(d[0]), "+f"(d[1]), "+f"(d[2]), "+f"(d[3])
        : "r"(a[0]), "r"(a[1]), "r"(a[2]), "r"(a[3]), "r"(b[0]), "r"(b[1]));
}

// ================= Kernel 0: weight transpose + bf16 split =================
// g_Wb[o][3*(k*256+c) + {0,1,2}] = (hi, hi, lo)
__global__ void __launch_bounds__(256) wt_kernel(const float* __restrict__ wc)
{
    int o = blockIdx.x;
    int c = threadIdx.x;
#pragma unroll
    for (int k = 0; k < 9; k++) {
        float w = __ldg(&wc[((size_t)o*C + c)*9 + k]);
        __nv_bfloat16 hi = __float2bfloat16(w);
        __nv_bfloat16 lo = __float2bfloat16(w - __bfloat162float(hi));
        size_t j3 = (size_t)3 * (k*C + c);
        __nv_bfloat16* p = &g_Wb[(size_t)o * KD3 + j3];
        p[0] = hi; p[1] = hi; p[2] = lo;
    }
}

// ================= Kernel 1: offset conv + position/weight precompute =================
__global__ void __launch_bounds__(256) offset_kernel(
    const float* __restrict__ x,  const float* __restrict__ w_p,
    const float* __restrict__ b_p, const float* __restrict__ w_ad,
    const float* __restrict__ b_ad)
{
    const int tid = threadIdx.x;
    const int tx  = tid & 63;
    const int ty  = tid >> 6;
    const int mA  = blockIdx.x * 128 + tx;
    const int mB  = mA + 64;

    __shared__ float wbuf[32][192];
    __shared__ float red[4][21][64];

    const int bA = mA / HW, hwA = mA % HW, hA = hwA / W, wA = hwA % W;
    const int bB = mB / HW, hwB = mB % HW, hB = hwB / W, wB = hwB % W;

    float acc[2][21];
#pragma unroll
    for (int p = 0; p < 2; p++)
#pragma unroll
        for (int oc = 0; oc < 21; oc++) acc[p][oc] = 0.f;

    const float* xA = x + (size_t)bA * C * HW;
    const float* xB = x + (size_t)bB * C * HW;

#pragma unroll 1
    for (int ch = 0; ch < 8; ch++) {
        __syncthreads();
        for (int idx = tid; idx < 32 * 189; idx += 256) {
            int row = idx / 189, e = idx % 189;
            int oc = e / 9, t = e % 9;
            int c = (row >> 3) * 64 + ch * 8 + (row & 7);
            float wv = (oc < 18) ? __ldg(&w_p[((size_t)oc*C + c)*9 + t])
                                 : __ldg(&w_ad[((size_t)(oc-18)*C + c)*9 + t]);
            wbuf[row][e] = wv;
        }
        __syncthreads();
#pragma unroll 1
        for (int cc = 0; cc < 8; cc++) {
            const int c = ty * 64 + ch * 8 + cc;
            const float* plA = xA + (size_t)c * HW;
            const float* plB = xB + (size_t)c * HW;
            float vA[9], vB[9];
#pragma unroll
            for (int t = 0; t < 9; t++) {
                int dh = t / 3 - 1, dw = t % 3 - 1;
                int h1 = hA + dh, w1 = wA + dw;
                vA[t] = (h1 >= 0 && h1 < H && w1 >= 0 && w1 < W) ? __ldg(&plA[h1*W + w1]) : 0.f;
                int h2 = hB + dh, w2 = wB + dw;
                vB[t] = (h2 >= 0 && h2 < H && w2 >= 0 && w2 < W) ? __ldg(&plB[h2*W + w2]) : 0.f;
            }
            const float* wr = &wbuf[ty * 8 + cc][0];
#pragma unroll
            for (int oc = 0; oc < 21; oc++) {
#pragma unroll
                for (int t = 0; t < 9; t++) {
                    float wv = wr[oc*9 + t];
                    acc[0][oc] += vA[t] * wv;
                    acc[1][oc] += vB[t] * wv;
                }
            }
        }
    }

#pragma unroll 1
    for (int p = 0; p < 2; p++) {
        __syncthreads();
#pragma unroll
        for (int oc = 0; oc < 21; oc++) red[ty][oc][tx] = acc[p][oc];
        __syncthreads();
        if (ty == 0) {
            const int m = (p == 0) ? mA : mB;
            const int h = (p == 0) ? hA : hB;
            const int w = (p == 0) ? wA : wB;
            float a[21];
#pragma unroll
            for (int oc = 0; oc < 21; oc++)
                a[oc] = red[0][oc][tx] + red[1][oc][tx] + red[2][oc][tx] + red[3][oc][tx];
#pragma unroll
            for (int k = 0; k < 9; k++) {
                float pnx = (float)(k / 3) - 1.f;
                float pny = (float)(k % 3) - 1.f;
                float z   = a[18 + (k % 3)] + __ldg(&b_ad[k % 3]);
                float sig = 1.f / (1.f + expf(-z));
                float ad  = 2.f * (1.f - sig);
                float px = (float)(h + 1) + pnx + a[k]     + __ldg(&b_p[k])     + ad * pnx;
                float py = (float)(w + 1) + pny + a[9 + k] + __ldg(&b_p[9 + k]) + ad * pny;
                float fx = floorf(px), fy = floorf(py);
                int iltx = (int)fx, ilty = (int)fy;
                int ltx = min(max(iltx,     0), HP - 1), lty = min(max(ilty,     0), HP - 1);
                int rbx = min(max(iltx + 1, 0), HP - 1), rby = min(max(ilty + 1, 0), HP - 1);
                bool mx = (px < 1.f) || (px > (float)(HP - 2));
                bool my = (py < 1.f) || (py > (float)(HP - 2));
                if (mx) px = fx;
                if (my) py = fy;
                px = fminf(fmaxf(px, 0.f), (float)(HP - 1));
                py = fminf(fmaxf(py, 0.f), (float)(HP - 1));
                float dxl = 1.f + ((float)ltx - px);
                float dyl = 1.f + ((float)lty - py);
                float dxr = 1.f - ((float)rbx - px);
                float dyr = 1.f - ((float)rby - py);
                g_qpack[k*MPIX + m] = (unsigned)ltx | ((unsigned)lty << 8)
                                    | ((unsigned)rbx << 16) | ((unsigned)rby << 24);
                g_w4[k*MPIX + m] = make_float4(dxl*dyl, dxr*dyr, dxl*dyr, dxr*dyl);
            }
        }
    }
}

// ================= Kernel 2: bilinear gather -> bf16 split X [m][j3] =================
__global__ void __launch_bounds__(256) sample_kernel(const float* __restrict__ x)
{
    const int tid = threadIdx.x;
    const int tx  = tid & 31;
    const int ty  = tid >> 5;                 // 0..7
    const int m   = blockIdx.x * 32 + tx;
    const int k   = blockIdx.z;
    const int c0  = blockIdx.y * 64;

    __shared__ __nv_bfloat16 st[32][194];     // row stride 194 bf16 (97 words, odd)

    const unsigned qp = g_qpack[k*MPIX + m];
    const float4 g = g_w4[k*MPIX + m];
    const int ltx = qp & 255, lty = (qp >> 8) & 255, rbx = (qp >> 16) & 255, rby = (qp >> 24) & 255;
    const bool ax  = (ltx >= 1) && (ltx <= 96);
    const bool axr = (rbx >= 1) && (rbx <= 96);
    const bool ay  = (lty >= 1) && (lty <= 96);
    const bool ayr = (rby >= 1) && (rby <= 96);
    const float glt = (ax  && ay ) ? g.x : 0.f;
    const float grb = (axr && ayr) ? g.y : 0.f;
    const float glb = (ax  && ayr) ? g.z : 0.f;
    const float grt = (axr && ay ) ? g.w : 0.f;
    const int oLT = (ax  && ay ) ? (ltx - 1) * W + (lty - 1) : 0;
    const int oRB = (axr && ayr) ? (rbx - 1) * W + (rby - 1) : 0;
    const int oLB = (ax  && ayr) ? (ltx - 1) * W + (rby - 1) : 0;
    const int oRT = (axr && ay ) ? (rbx - 1) * W + (lty - 1) : 0;
    const int b = m / HW;
    const float* xb = x + (size_t)(b * C + c0 + ty * 8) * HW;

#pragma unroll
    for (int cc = 0; cc < 8; cc++) {
        const float* pl = xb + (size_t)cc * HW;
        float v = glt * __ldg(&pl[oLT]) + grb * __ldg(&pl[oRB])
                + glb * __ldg(&pl[oLB]) + grt * __ldg(&pl[oRT]);
        __nv_bfloat16 hi = __float2bfloat16(v);
        __nv_bfloat16 lo = __float2bfloat16(v - __bfloat162float(hi));
        int col = (ty * 8 + cc) * 3;
        st[tx][col]     = hi;     // pairs with W hi -> hi*hi
        st[tx][col + 1] = lo;     // pairs with W hi -> lo*hi
        st[tx][col + 2] = hi;     // pairs with W lo -> hi*lo
    }
    __syncthreads();

    const size_t j3base = (size_t)3 * (k*C + c0);
#pragma unroll
    for (int i = 0; i < 12; i++) {
        int idx = tid + i * 256;
        int row = idx / 96, wrd = idx % 96;
        uint32_t* dst = (uint32_t*)&g_Xb[(size_t)(blockIdx.x*32 + row) * KD3 + j3base];
        dst[wrd] = ((const uint32_t*)&st[row][0])[wrd];
    }
}

// ================= Kernel 3: HMMA (mma.sync bf16) GEMM =================
// Per CTA: D[128 m][128 o] = A[128 m][K] x B[128 o][K]^T, K = 6912 bf16.
#define GBK 64
#define GNKIT (KD3 / GBK)     // 108
#define GNST 3
#define GA_BYTES (128 * 128)  // 16KB
#define GSTG (2 * GA_BYTES)   // 32KB (A then B)
#define GEMM_SMEM (GNST * GSTG)  // 96KB

__device__ __forceinline__ void load_stage_g(uint32_t abase, const char* Ag, const char* Bg,
                                             int t, int tid)
{
    const size_t pitch = (size_t)KD3 * 2;      // 13824 B
    const size_t koff = (size_t)t * 128;       // 64 bf16
#pragma unroll
    for (int j = 0; j < 4; j++) {              // A: 1024 x 16B
        int idx = tid + j * 256;
        int r = idx >> 3, cc = idx & 7;
        uint32_t off = (uint32_t)(r * 128 + cc * 16);
        uint32_t sw = off ^ ((off >> 3) & 0x70);
        cp16(abase + sw, Ag + (size_t)r * pitch + koff + cc * 16);
    }
#pragma unroll
    for (int j = 0; j < 4; j++) {              // B: 1024 x 16B
        int idx = tid + j * 256;
        int r = idx >> 3, cc = idx & 7;
        uint32_t off = (uint32_t)(r * 128 + cc * 16);
        uint32_t sw = off ^ ((off >> 3) & 0x70);
        cp16(abase + GA_BYTES + sw, Bg + (size_t)r * pitch + koff + cc * 16);
    }
    cp_commit();
}

__global__ void __launch_bounds__(256, 2) mma_kernel(float* __restrict__ out)
{
    extern __shared__ char smem[];
    const uint32_t sb = smem_u32(smem);
    const int tid = threadIdx.x;
    const int wid = tid >> 5, lane = tid & 31;
    const int m0 = blockIdx.x * 128;
    const int o0 = blockIdx.y * 128;

    const char* Ag = (const char*)&g_Xb[(size_t)m0 * KD3];
    const char* Bg = (const char*)&g_Wb[(size_t)o0 * KD3];

    const int wm = (wid >> 2) * 64;   // warp m offset (0/64)
    const int wn = (wid & 3) * 32;    // warp n offset (0/32/64/96)

    float acc[4][4][4];
#pragma unroll
    for (int mi = 0; mi < 4; mi++)
#pragma unroll
        for (int ni = 0; ni < 4; ni++)
#pragma unroll
            for (int r = 0; r < 4; r++) acc[mi][ni][r] = 0.f;

    // per-lane ldmatrix row/col components (byte offsets before swizzle)
    const int a_row = wm + (lane & 15);            // + mi*16
    const int a_cb  = (lane >> 4) * 16;            // + kk*32
    const int b_row = wn + (lane & 7) + ((lane >> 4) << 3);  // + nb*16
    const int b_cb  = ((lane >> 3) & 1) * 16;      // + kk*32

    load_stage_g(sb,        Ag, Bg, 0, tid);
    load_stage_g(sb + GSTG, Ag, Bg, 1, tid);

#pragma unroll 1
    for (int t = 0; t < GNKIT; t++) {
        if (t + 1 < GNKIT) cp_wait<1>(); else cp_wait<0>();
        __syncthreads();
        const uint32_t abase = sb + (t % GNST) * GSTG;
        const uint32_t bbase = abase + GA_BYTES;
#pragma unroll
        for (int kk = 0; kk < 4; kk++) {
            const int kb = kk * 32;
            uint32_t a[4][4], bfr[2][4];
#pragma unroll
            for (int mi = 0; mi < 4; mi++) {
                uint32_t off = (uint32_t)((a_row + mi * 16) * 128 + kb + a_cb);
                ldsm_x4(a[mi], abase + (off ^ ((off >> 3) & 0x70)));
            }
#pragma unroll
            for (int nb = 0; nb < 2; nb++) {
                uint32_t off = (uint32_t)((b_row + nb * 16) * 128 + kb + b_cb);
                ldsm_x4(bfr[nb], bbase + (off ^ ((off >> 3) & 0x70)));
            }
#pragma unroll
            for (int mi = 0; mi < 4; mi++)
#pragma unroll
                for (int ni = 0; ni < 4; ni++)
                    mma16816(acc[mi][ni], a[mi], &bfr[ni >> 1][(ni & 1) * 2]);
        }
        int u = t + 2;
        if (u < GNKIT) load_stage_g(sb + (u % GNST) * GSTG, Ag, Bg, u, tid);
    }

    // ---- epilogue: smem transpose to [o][m] then coalesced stores ----
    __syncthreads();
    float* eb = (float*)smem;                 // 128 x 132 floats = 67.6KB (fits 96KB)
    const int er = lane >> 2;                 // frag row within 8
    const int ec = (lane & 3) * 2;            // frag col pair
#pragma unroll
    for (int mi = 0; mi < 4; mi++) {
#pragma unroll
        for (int ni = 0; ni < 4; ni++) {
            int m = wm + mi * 16 + er;
            int o = wn + ni * 8 + ec;
            eb[(o    ) * 132 + m    ] = acc[mi][ni][0];
            eb[(o + 1) * 132 + m    ] = acc[mi][ni][1];
            eb[(o    ) * 132 + m + 8] = acc[mi][ni][2];
            eb[(o + 1) * 132 + m + 8] = acc[mi][ni][3];
        }
    }
    __syncthreads();
    const int b   = m0 / HW;                  // 128 | HW -> no straddle
    const int hw0 = m0 % HW;
#pragma unroll
    for (int i = 0; i < 16; i++) {
        int idx = tid + i * 256;
        int r = idx >> 5, c4 = (idx & 31) * 4;
        float4 v = *(const float4*)&eb[r * 132 + c4];
        *(float4*)&out[(size_t)(b * OC + o0 + r) * HW + hw0 + c4] = v;
    }
}

// ================= launch =================
extern "C" void kernel_launch(void* const* d_in, const int* in_sizes, int n_in,
                              void* d_out, int out_size)
{
    const float* x      = (const float*)d_in[0];
    const float* w_p    = (const float*)d_in[1];
    const float* b_p    = (const float*)d_in[2];
    const float* w_ad   = (const float*)d_in[3];
    const float* b_ad   = (const float*)d_in[4];
    const float* w_conv = (const float*)d_in[5];
    float* out = (float*)d_out;

    cudaFuncSetAttribute(mma_kernel, cudaFuncAttributeMaxDynamicSharedMemorySize, GEMM_SMEM);

    wt_kernel<<<OC, C>>>(w_conv);
    offset_kernel<<<MPIX / 128, 256>>>(x, w_p, b_p, w_ad, b_ad);
    sample_kernel<<<dim3(MPIX / 32, C / 64, NTAP), 256>>>(x);
    mma_kernel<<<dim3(MPIX / 128, OC / 128), 256, GEMM_SMEM>>>(out);
}

// round 5
// speedup vs baseline: 2.0180x; 1.0484x over previous
#include <cuda_runtime.h>
#include <cuda_bf16.h>
#include <cstdint>

#define BDIM 2
#define C 256
#define H 96
#define W 96
#define HW (H*W)          // 9216
#define MPIX (BDIM*HW)    // 18432
#define OC 256
#define NTAP 9
#define KD3 (NTAP*C*3)    // 6912 (K expanded 3x for split-bf16)
#define HP 98

// -------- scratch (static device globals; no allocations) --------
__device__ __align__(128) __nv_bfloat16 g_Xb[(size_t)MPIX * KD3]; // [m][j3] ~255MB
__device__ __align__(128) __nv_bfloat16 g_Wb[(size_t)OC * KD3];   // [o][j3] ~3.5MB
__device__ __align__(128) float g_xT[(size_t)MPIX * C];           // NHWC transpose of x (19MB)
__device__ unsigned int g_qpack[NTAP * MPIX];
__device__ float4       g_w4[NTAP * MPIX];

// ---------------- PTX helpers (base ISA only) ----------------
__device__ __forceinline__ uint32_t smem_u32(const void* p) {
    uint32_t a;
    asm("{ .reg .u64 t; cvta.to.shared.u64 t, %1; cvt.u32.u64 %0, t; }" : "=r"(a) : "l"(p));
    return a;
}
__device__ __forceinline__ void cp16(uint32_t s, const void* g) {
    asm volatile("cp.async.cg.shared.global [%0], [%1], 16;" :: "r"(s), "l"(g));
}
__device__ __forceinline__ void cp_commit() {
    asm volatile("cp.async.commit_group;" ::: "memory");
}
template <int N> __device__ __forceinline__ void cp_wait() {
    asm volatile("cp.async.wait_group %0;" :: "n"(N) : "memory");
}
__device__ __forceinline__ void ldsm_x4(uint32_t* r, uint32_t addr) {
    asm volatile("ldmatrix.sync.aligned.m8n8.x4.shared.b16 {%0,%1,%2,%3}, [%4];"
        : "=r"(r[0]), "=r"(r[1]), "=r"(r[2]), "=r"(r[3]) : "r"(addr));
}
__device__ __forceinline__ void mma16816(float* d, const uint32_t* a, const uint32_t* b) {
    asm volatile("mma.sync.aligned.m16n8k16.row.col.f32.bf16.bf16.f32 "
        "{%0,%1,%2,%3}, {%4,%5,%6,%7}, {%8,%9}, {%0,%1,%2,%3};"
        : "+f"(d[0]), "+f"(d[1]), "+f"(d[2]), "+f"(d[3])
        : "r"(a[0]), "r"(a[1]), "r"(a[2]), "r"(a[3]), "r"(b[0]), "r"(b[1]));
}

// ================= Kernel 0: weight transpose + bf16 split =================
__global__ void __launch_bounds__(256) wt_kernel(const float* __restrict__ wc)
{
    int o = blockIdx.x;
    int c = threadIdx.x;
#pragma unroll
    for (int k = 0; k < 9; k++) {
        float w = __ldg(&wc[((size_t)o*C + c)*9 + k]);
        __nv_bfloat16 hi = __float2bfloat16(w);
        __nv_bfloat16 lo = __float2bfloat16(w - __bfloat162float(hi));
        size_t j3 = (size_t)3 * (k*C + c);
        __nv_bfloat16* p = &g_Wb[(size_t)o * KD3 + j3];
        p[0] = hi; p[1] = hi; p[2] = lo;
    }
}

// ================= Kernel 0b: NCHW -> NHWC transpose =================
// xT[(b*HW + hw)*C + c] = x[(b*C + c)*HW + hw]
__global__ void __launch_bounds__(256) tr_kernel(const float* __restrict__ x)
{
    __shared__ float tile[32][33];
    const int b   = blockIdx.z;
    const int c0  = blockIdx.y * 32;
    const int hw0 = blockIdx.x * 32;
    const int tx = threadIdx.x & 31;     // hw / c inner
    const int ty = threadIdx.x >> 5;     // 8 rows per pass
#pragma unroll
    for (int r = 0; r < 4; r++) {
        int c = c0 + ty + r * 8;
        tile[ty + r * 8][tx] = x[(size_t)(b * C + c) * HW + hw0 + tx];
    }
    __syncthreads();
#pragma unroll
    for (int r = 0; r < 4; r++) {
        int hw = hw0 + ty + r * 8;
        g_xT[(size_t)(b * HW + hw) * C + c0 + tx] = tile[tx][ty + r * 8];
    }
}

// ================= Kernel 1: offset conv + position/weight precompute =================
__global__ void __launch_bounds__(256) offset_kernel(
    const float* __restrict__ x,  const float* __restrict__ w_p,
    const float* __restrict__ b_p, const float* __restrict__ w_ad,
    const float* __restrict__ b_ad)
{
    const int tid = threadIdx.x;
    const int tx  = tid & 63;
    const int ty  = tid >> 6;
    const int mA  = blockIdx.x * 128 + tx;
    const int mB  = mA + 64;

    __shared__ float wbuf[32][192];
    __shared__ float red[4][21][64];

    const int bA = mA / HW, hwA = mA % HW, hA = hwA / W, wA = hwA % W;
    const int bB = mB / HW, hwB = mB % HW, hB = hwB / W, wB = hwB % W;

    float acc[2][21];
#pragma unroll
    for (int p = 0; p < 2; p++)
#pragma unroll
        for (int oc = 0; oc < 21; oc++) acc[p][oc] = 0.f;

    const float* xA = x + (size_t)bA * C * HW;
    const float* xB = x + (size_t)bB * C * HW;

#pragma unroll 1
    for (int ch = 0; ch < 8; ch++) {
        __syncthreads();
        for (int idx = tid; idx < 32 * 189; idx += 256) {
            int row = idx / 189, e = idx % 189;
            int oc = e / 9, t = e % 9;
            int c = (row >> 3) * 64 + ch * 8 + (row & 7);
            float wv = (oc < 18) ? __ldg(&w_p[((size_t)oc*C + c)*9 + t])
                                 : __ldg(&w_ad[((size_t)(oc-18)*C + c)*9 + t]);
            wbuf[row][e] = wv;
        }
        __syncthreads();
#pragma unroll 1
        for (int cc = 0; cc < 8; cc++) {
            const int c = ty * 64 + ch * 8 + cc;
            const float* plA = xA + (size_t)c * HW;
            const float* plB = xB + (size_t)c * HW;
            float vA[9], vB[9];
#pragma unroll
            for (int t = 0; t < 9; t++) {
                int dh = t / 3 - 1, dw = t % 3 - 1;
                int h1 = hA + dh, w1 = wA + dw;
                vA[t] = (h1 >= 0 && h1 < H && w1 >= 0 && w1 < W) ? __ldg(&plA[h1*W + w1]) : 0.f;
                int h2 = hB + dh, w2 = wB + dw;
                vB[t] = (h2 >= 0 && h2 < H && w2 >= 0 && w2 < W) ? __ldg(&plB[h2*W + w2]) : 0.f;
            }
            const float* wr = &wbuf[ty * 8 + cc][0];
#pragma unroll
            for (int oc = 0; oc < 21; oc++) {
#pragma unroll
                for (int t = 0; t < 9; t++) {
                    float wv = wr[oc*9 + t];
                    acc[0][oc] += vA[t] * wv;
                    acc[1][oc] += vB[t] * wv;
                }
            }
        }
    }

#pragma unroll 1
    for (int p = 0; p < 2; p++) {
        __syncthreads();
#pragma unroll
        for (int oc = 0; oc < 21; oc++) red[ty][oc][tx] = acc[p][oc];
        __syncthreads();
        if (ty == 0) {
            const int m = (p == 0) ? mA : mB;
            const int h = (p == 0) ? hA : hB;
            const int w = (p == 0) ? wA : wB;
            float a[21];
#pragma unroll
            for (int oc = 0; oc < 21; oc++)
                a[oc] = red[0][oc][tx] + red[1][oc][tx] + red[2][oc][tx] + red[3][oc][tx];
#pragma unroll
            for (int k = 0; k < 9; k++) {
                float pnx = (float)(k / 3) - 1.f;
                float pny = (float)(k % 3) - 1.f;
                float z   = a[18 + (k % 3)] + __ldg(&b_ad[k % 3]);
                float sig = 1.f / (1.f + expf(-z));
                float ad  = 2.f * (1.f - sig);
                float px = (float)(h + 1) + pnx + a[k]     + __ldg(&b_p[k])     + ad * pnx;
                float py = (float)(w + 1) + pny + a[9 + k] + __ldg(&b_p[9 + k]) + ad * pny;
                float fx = floorf(px), fy = floorf(py);
                int iltx = (int)fx, ilty = (int)fy;
                int ltx = min(max(iltx,     0), HP - 1), lty = min(max(ilty,     0), HP - 1);
                int rbx = min(max(iltx + 1, 0), HP - 1), rby = min(max(ilty + 1, 0), HP - 1);
                bool mx = (px < 1.f) || (px > (float)(HP - 2));
                bool my = (py < 1.f) || (py > (float)(HP - 2));
                if (mx) px = fx;
                if (my) py = fy;
                px = fminf(fmaxf(px, 0.f), (float)(HP - 1));
                py = fminf(fmaxf(py, 0.f), (float)(HP - 1));
                float dxl = 1.f + ((float)ltx - px);
                float dyl = 1.f + ((float)lty - py);
                float dxr = 1.f - ((float)rbx - px);
                float dyr = 1.f - ((float)rby - py);
                g_qpack[k*MPIX + m] = (unsigned)ltx | ((unsigned)lty << 8)
                                    | ((unsigned)rbx << 16) | ((unsigned)rby << 24);
                g_w4[k*MPIX + m] = make_float4(dxl*dyl, dxr*dyr, dxl*dyr, dxr*dyl);
            }
        }
    }
}

// ================= Kernel 2: bilinear gather (NHWC) -> bf16 split X =================
// One warp per (m,k): 4 corner rows of 256 contiguous channels each.
__global__ void __launch_bounds__(256) sample_kernel()
{
    __shared__ __nv_bfloat16 st[8][768];      // 1536B per warp

    const int tid  = threadIdx.x;
    const int wid  = tid >> 5, lane = tid & 31;
    const int pid  = blockIdx.x * 8 + wid;    // (m,k) pair id
    const int k    = pid / MPIX;
    const int m    = pid % MPIX;

    const unsigned qp = g_qpack[k*MPIX + m];
    const float4 g = g_w4[k*MPIX + m];
    const int ltx = qp & 255, lty = (qp >> 8) & 255, rbx = (qp >> 16) & 255, rby = (qp >> 24) & 255;
    const bool ax  = (ltx >= 1) && (ltx <= 96);
    const bool axr = (rbx >= 1) && (rbx <= 96);
    const bool ay  = (lty >= 1) && (lty <= 96);
    const bool ayr = (rby >= 1) && (rby <= 96);
    const float glt = (ax  && ay ) ? g.x : 0.f;
    const float grb = (axr && ayr) ? g.y : 0.f;
    const float glb = (ax  && ayr) ? g.z : 0.f;
    const float grt = (axr && ay ) ? g.w : 0.f;
    const int b = m / HW;
    const size_t base = (size_t)b * HW * C;
    const size_t oLT = (ax  && ay ) ? base + (size_t)((ltx-1)*W + (lty-1)) * C : base;
    const size_t oRB = (axr && ayr) ? base + (size_t)((rbx-1)*W + (rby-1)) * C : base;
    const size_t oLB = (ax  && ayr) ? base + (size_t)((ltx-1)*W + (rby-1)) * C : base;
    const size_t oRT = (axr && ay ) ? base + (size_t)((rbx-1)*W + (lty-1)) * C : base;

    const int c0 = lane * 8;
    float4 vLT0 = *(const float4*)&g_xT[oLT + c0];
    float4 vLT1 = *(const float4*)&g_xT[oLT + c0 + 4];
    float4 vRB0 = *(const float4*)&g_xT[oRB + c0];
    float4 vRB1 = *(const float4*)&g_xT[oRB + c0 + 4];
    float4 vLB0 = *(const float4*)&g_xT[oLB + c0];
    float4 vLB1 = *(const float4*)&g_xT[oLB + c0 + 4];
    float4 vRT0 = *(const float4*)&g_xT[oRT + c0];
    float4 vRT1 = *(const float4*)&g_xT[oRT + c0 + 4];

    float v[8];
    v[0] = glt*vLT0.x + grb*vRB0.x + glb*vLB0.x + grt*vRT0.x;
    v[1] = glt*vLT0.y + grb*vRB0.y + glb*vLB0.y + grt*vRT0.y;
    v[2] = glt*vLT0.z + grb*vRB0.z + glb*vLB0.z + grt*vRT0.z;
    v[3] = glt*vLT0.w + grb*vRB0.w + glb*vLB0.w + grt*vRT0.w;
    v[4] = glt*vLT1.x + grb*vRB1.x + glb*vLB1.x + grt*vRT1.x;
    v[5] = glt*vLT1.y + grb*vRB1.y + glb*vLB1.y + grt*vRT1.y;
    v[6] = glt*vLT1.z + grb*vRB1.z + glb*vLB1.z + grt*vRT1.z;
    v[7] = glt*vLT1.w + grb*vRB1.w + glb*vLB1.w + grt*vRT1.w;

#pragma unroll
    for (int j = 0; j < 8; j++) {
        __nv_bfloat16 hi = __float2bfloat16(v[j]);
        __nv_bfloat16 lo = __float2bfloat16(v[j] - __bfloat162float(hi));
        int col = (c0 + j) * 3;
        st[wid][col]     = hi;
        st[wid][col + 1] = lo;
        st[wid][col + 2] = hi;
    }
    __syncwarp();

    // coalesced write: 1536B per warp = 96 uint4, 3 per lane
    uint4* dst = (uint4*)&g_Xb[(size_t)m * KD3 + (size_t)3 * k * C];
    const uint4* src = (const uint4*)&st[wid][0];
#pragma unroll
    for (int i = 0; i < 3; i++)
        dst[lane + i * 32] = src[lane + i * 32];
}

// ================= Kernel 3: HMMA (mma.sync bf16) GEMM =================
#define GBK 64
#define GNKIT (KD3 / GBK)     // 108
#define GNST 3
#define GA_BYTES (128 * 128)  // 16KB
#define GSTG (2 * GA_BYTES)   // 32KB (A then B)
#define GEMM_SMEM (GNST * GSTG)  // 96KB

__device__ __forceinline__ void load_stage_g(uint32_t abase, const char* Ag, const char* Bg,
                                             int t, int tid)
{
    const size_t pitch = (size_t)KD3 * 2;      // 13824 B
    const size_t koff = (size_t)t * 128;       // 64 bf16
#pragma unroll
    for (int j = 0; j < 4; j++) {
        int idx = tid + j * 256;
        int r = idx >> 3, cc = idx & 7;
        uint32_t off = (uint32_t)(r * 128 + cc * 16);
        uint32_t sw = off ^ ((off >> 3) & 0x70);
        cp16(abase + sw, Ag + (size_t)r * pitch + koff + cc * 16);
    }
#pragma unroll
    for (int j = 0; j < 4; j++) {
        int idx = tid + j * 256;
        int r = idx >> 3, cc = idx & 7;
        uint32_t off = (uint32_t)(r * 128 + cc * 16);
        uint32_t sw = off ^ ((off >> 3) & 0x70);
        cp16(abase + GA_BYTES + sw, Bg + (size_t)r * pitch + koff + cc * 16);
    }
    cp_commit();
}

__global__ void __launch_bounds__(256, 2) mma_kernel(float* __restrict__ out)
{
    extern __shared__ char smem[];
    const uint32_t sb = smem_u32(smem);
    const int tid = threadIdx.x;
    const int wid = tid >> 5, lane = tid & 31;
    const int m0 = blockIdx.x * 128;
    const int o0 = blockIdx.y * 128;

    const char* Ag = (const char*)&g_Xb[(size_t)m0 * KD3];
    const char* Bg = (const char*)&g_Wb[(size_t)o0 * KD3];

    const int wm = (wid >> 2) * 64;
    const int wn = (wid & 3) * 32;

    float acc[4][4][4];
#pragma unroll
    for (int mi = 0; mi < 4; mi++)
#pragma unroll
        for (int ni = 0; ni < 4; ni++)
#pragma unroll
            for (int r = 0; r < 4; r++) acc[mi][ni][r] = 0.f;

    const int a_row = wm + (lane & 15);
    const int a_cb  = (lane >> 4) * 16;
    const int b_row = wn + (lane & 7) + ((lane >> 4) << 3);
    const int b_cb  = ((lane >> 3) & 1) * 16;

    load_stage_g(sb,        Ag, Bg, 0, tid);
    load_stage_g(sb + GSTG, Ag, Bg, 1, tid);

#pragma unroll 1
    for (int t = 0; t < GNKIT; t++) {
        if (t + 1 < GNKIT) cp_wait<1>(); else cp_wait<0>();
        __syncthreads();
        const uint32_t abase = sb + (t % GNST) * GSTG;
        const uint32_t bbase = abase + GA_BYTES;
#pragma unroll
        for (int kk = 0; kk < 4; kk++) {
            const int kb = kk * 32;
            uint32_t a[4][4], bfr[2][4];
#pragma unroll
            for (int mi = 0; mi < 4; mi++) {
                uint32_t off = (uint32_t)((a_row + mi * 16) * 128 + kb + a_cb);
                ldsm_x4(a[mi], abase + (off ^ ((off >> 3) & 0x70)));
            }
#pragma unroll
            for (int nb = 0; nb < 2; nb++) {
                uint32_t off = (uint32_t)((b_row + nb * 16) * 128 + kb + b_cb);
                ldsm_x4(bfr[nb], bbase + (off ^ ((off >> 3) & 0x70)));
            }
#pragma unroll
            for (int mi = 0; mi < 4; mi++)
#pragma unroll
                for (int ni = 0; ni < 4; ni++)
                    mma16816(acc[mi][ni], a[mi], &bfr[ni >> 1][(ni & 1) * 2]);
        }
        int u = t + 2;
        if (u < GNKIT) load_stage_g(sb + (u % GNST) * GSTG, Ag, Bg, u, tid);
    }

    __syncthreads();
    float* eb = (float*)smem;
    const int er = lane >> 2;
    const int ec = (lane & 3) * 2;
#pragma unroll
    for (int mi = 0; mi < 4; mi++) {
#pragma unroll
        for (int ni = 0; ni < 4; ni++) {
            int m = wm + mi * 16 + er;
            int o = wn + ni * 8 + ec;
            eb[(o    ) * 132 + m    ] = acc[mi][ni][0];
            eb[(o + 1) * 132 + m    ] = acc[mi][ni][1];
            eb[(o    ) * 132 + m + 8] = acc[mi][ni][2];
            eb[(o + 1) * 132 + m + 8] = acc[mi][ni][3];
        }
    }
    __syncthreads();
    const int b   = m0 / HW;
    const int hw0 = m0 % HW;
#pragma unroll
    for (int i = 0; i < 16; i++) {
        int idx = tid + i * 256;
        int r = idx >> 5, c4 = (idx & 31) * 4;
        float4 v = *(const float4*)&eb[r * 132 + c4];
        *(float4*)&out[(size_t)(b * OC + o0 + r) * HW + hw0 + c4] = v;
    }
}

// ================= launch =================
extern "C" void kernel_launch(void* const* d_in, const int* in_sizes, int n_in,
                              void* d_out, int out_size)
{
    const float* x      = (const float*)d_in[0];
    const float* w_p    = (const float*)d_in[1];
    const float* b_p    = (const float*)d_in[2];
    const float* w_ad   = (const float*)d_in[3];
    const float* b_ad   = (const float*)d_in[4];
    const float* w_conv = (const float*)d_in[5];
    float* out = (float*)d_out;

    cudaFuncSetAttribute(mma_kernel, cudaFuncAttributeMaxDynamicSharedMemorySize, GEMM_SMEM);

    wt_kernel<<<OC, C>>>(w_conv);
    tr_kernel<<<dim3(HW / 32, C / 32, BDIM), 256>>>(x);
    offset_kernel<<<MPIX / 128, 256>>>(x, w_p, b_p, w_ad, b_ad);
    sample_kernel<<<MPIX * NTAP / 8, 256>>>();
    mma_kernel<<<dim3(MPIX / 128, OC / 128), 256, GEMM_SMEM>>>(out);
}

// round 6
// speedup vs baseline: 2.2487x; 1.1143x over previous
#include <cuda_runtime.h>
#include <cuda_bf16.h>
#include <cstdint>

#define BDIM 2
#define C 256
#define H 96
#define W 96
#define HW (H*W)          // 9216
#define MPIX (BDIM*HW)    // 18432
#define OC 256
#define NTAP 9
#define KD3 (NTAP*C*3)    // 6912 (K expanded 3x for split-bf16)
#define HP 98

// -------- scratch (static device globals; no allocations) --------
__device__ __align__(128) __nv_bfloat16 g_Xb[(size_t)MPIX * KD3]; // [m][j3] ~255MB
__device__ __align__(128) __nv_bfloat16 g_Wb[(size_t)OC * KD3];   // [o][j3] ~3.5MB
__device__ __align__(128) float g_xT[(size_t)MPIX * C];           // NHWC transpose of x (19MB)
__device__ unsigned int g_qpack[NTAP * MPIX];
__device__ float4       g_w4[NTAP * MPIX];

// ---------------- PTX helpers (base ISA only) ----------------
__device__ __forceinline__ uint32_t smem_u32(const void* p) {
    uint32_t a;
    asm("{ .reg .u64 t; cvta.to.shared.u64 t, %1; cvt.u32.u64 %0, t; }" : "=r"(a) : "l"(p));
    return a;
}
__device__ __forceinline__ void cp16(uint32_t s, const void* g) {
    asm volatile("cp.async.cg.shared.global [%0], [%1], 16;" :: "r"(s), "l"(g));
}
__device__ __forceinline__ void cp_commit() {
    asm volatile("cp.async.commit_group;" ::: "memory");
}
template <int N> __device__ __forceinline__ void cp_wait() {
    asm volatile("cp.async.wait_group %0;" :: "n"(N) : "memory");
}
__device__ __forceinline__ void ldsm_x4(uint32_t* r, uint32_t addr) {
    asm volatile("ldmatrix.sync.aligned.m8n8.x4.shared.b16 {%0,%1,%2,%3}, [%4];"
        : "=r"(r[0]), "=r"(r[1]), "=r"(r[2]), "=r"(r[3]) : "r"(addr));
}
__device__ __forceinline__ void mma16816(float* d, const uint32_t* a, const uint32_t* b) {
    asm volatile("mma.sync.aligned.m16n8k16.row.col.f32.bf16.bf16.f32 "
        "{%0,%1,%2,%3}, {%4,%5,%6,%7}, {%8,%9}, {%0,%1,%2,%3};"
        : "+f"(d[0]), "+f"(d[1]), "+f"(d[2]), "+f"(d[3])
        : "r"(a[0]), "r"(a[1]), "r"(a[2]), "r"(a[3]), "r"(b[0]), "r"(b[1]));
}
__device__ __forceinline__ unsigned long long fma2(
    unsigned long long a, unsigned long long b, unsigned long long c)
{
    unsigned long long d;
    asm("fma.rn.f32x2 %0, %1, %2, %3;" : "=l"(d) : "l"(a), "l"(b), "l"(c));
    return d;
}
__device__ __forceinline__ unsigned long long pack2(float v) {
    unsigned long long d;
    asm("mov.b64 %0, {%1, %1};" : "=l"(d) : "f"(v));
    return d;
}

// ================= Kernel 0: weight transpose + bf16 split =================
__global__ void __launch_bounds__(256) wt_kernel(const float* __restrict__ wc)
{
    int o = blockIdx.x;
    int c = threadIdx.x;
#pragma unroll
    for (int k = 0; k < 9; k++) {
        float w = __ldg(&wc[((size_t)o*C + c)*9 + k]);
        __nv_bfloat16 hi = __float2bfloat16(w);
        __nv_bfloat16 lo = __float2bfloat16(w - __bfloat162float(hi));
        size_t j3 = (size_t)3 * (k*C + c);
        __nv_bfloat16* p = &g_Wb[(size_t)o * KD3 + j3];
        p[0] = hi; p[1] = hi; p[2] = lo;
    }
}

// ================= Kernel 0b: NCHW -> NHWC transpose =================
__global__ void __launch_bounds__(256) tr_kernel(const float* __restrict__ x)
{
    __shared__ float tile[32][33];
    const int b   = blockIdx.z;
    const int c0  = blockIdx.y * 32;
    const int hw0 = blockIdx.x * 32;
    const int tx = threadIdx.x & 31;
    const int ty = threadIdx.x >> 5;
#pragma unroll
    for (int r = 0; r < 4; r++) {
        int c = c0 + ty + r * 8;
        tile[ty + r * 8][tx] = x[(size_t)(b * C + c) * HW + hw0 + tx];
    }
    __syncthreads();
#pragma unroll
    for (int r = 0; r < 4; r++) {
        int hw = hw0 + ty + r * 8;
        g_xT[(size_t)(b * HW + hw) * C + c0 + tx] = tile[tx][ty + r * 8];
    }
}

// ================= Kernel 1: offset conv (f32x2, oc-pair accum) =================
__global__ void __launch_bounds__(256) offset_kernel(
    const float* __restrict__ x,  const float* __restrict__ w_p,
    const float* __restrict__ b_p, const float* __restrict__ w_ad,
    const float* __restrict__ b_ad)
{
    const int tid = threadIdx.x;
    const int tx  = tid & 63;
    const int ty  = tid >> 6;
    const int mA  = blockIdx.x * 128 + tx;
    const int mB  = mA + 64;

    __shared__ float wbuf[32][200];   // [s*8+cc][t*22 + oc], oc padded to 22
    __shared__ float red[4][21][64];

    const int bA = mA / HW, hwA = mA % HW, hA = hwA / W, wA = hwA % W;
    const int bB = mB / HW, hwB = mB % HW, hB = hwB / W, wB = hwB % W;

    unsigned long long accA[11], accB[11];
#pragma unroll
    for (int i = 0; i < 11; i++) { accA[i] = 0ull; accB[i] = 0ull; }

    // zero the pad slot (oc=21) once; never overwritten by staging
    if (tid < 32) {
#pragma unroll
        for (int t = 0; t < 9; t++) wbuf[tid][t*22 + 21] = 0.f;
    }

    const float* xA = x + (size_t)bA * C * HW;
    const float* xB = x + (size_t)bB * C * HW;

#pragma unroll 1
    for (int ch = 0; ch < 8; ch++) {
        __syncthreads();
        for (int idx = tid; idx < 32 * 189; idx += 256) {
            int row = idx / 189, e = idx % 189;
            int oc = e / 9, t = e % 9;
            int c = (row >> 3) * 64 + ch * 8 + (row & 7);
            float wv = (oc < 18) ? __ldg(&w_p[((size_t)oc*C + c)*9 + t])
                                 : __ldg(&w_ad[((size_t)(oc-18)*C + c)*9 + t]);
            wbuf[row][t*22 + oc] = wv;
        }
        __syncthreads();
#pragma unroll 1
        for (int cc = 0; cc < 8; cc++) {
            const int c = ty * 64 + ch * 8 + cc;
            const float* plA = xA + (size_t)c * HW;
            const float* plB = xB + (size_t)c * HW;
            float vA[9], vB[9];
#pragma unroll
            for (int t = 0; t < 9; t++) {
                int dh = t / 3 - 1, dw = t % 3 - 1;
                int h1 = hA + dh, w1 = wA + dw;
                vA[t] = (h1 >= 0 && h1 < H && w1 >= 0 && w1 < W) ? __ldg(&plA[h1*W + w1]) : 0.f;
                int h2 = hB + dh, w2 = wB + dw;
                vB[t] = (h2 >= 0 && h2 < H && w2 >= 0 && w2 < W) ? __ldg(&plB[h2*W + w2]) : 0.f;
            }
            const float* wr = &wbuf[ty * 8 + cc][0];
#pragma unroll
            for (int t = 0; t < 9; t++) {
                unsigned long long aA = pack2(vA[t]);
                unsigned long long aB = pack2(vB[t]);
#pragma unroll
                for (int o2 = 0; o2 < 11; o2++) {
                    unsigned long long wpair =
                        *(const unsigned long long*)&wr[t*22 + o2*2];
                    accA[o2] = fma2(wpair, aA, accA[o2]);
                    accB[o2] = fma2(wpair, aB, accB[o2]);
                }
            }
        }
    }

#pragma unroll 1
    for (int p = 0; p < 2; p++) {
        __syncthreads();
#pragma unroll
        for (int o2 = 0; o2 < 11; o2++) {
            unsigned long long v = p ? accB[o2] : accA[o2];
            float lo = __uint_as_float((unsigned)(v & 0xffffffffull));
            float hi = __uint_as_float((unsigned)(v >> 32));
            red[ty][o2*2][tx] = lo;
            if (o2 < 10) red[ty][o2*2+1][tx] = hi;
        }
        __syncthreads();
        if (ty == 0) {
            const int m = (p == 0) ? mA : mB;
            const int h = (p == 0) ? hA : hB;
            const int w = (p == 0) ? wA : wB;
            float a[21];
#pragma unroll
            for (int oc = 0; oc < 21; oc++)
                a[oc] = red[0][oc][tx] + red[1][oc][tx] + red[2][oc][tx] + red[3][oc][tx];
#pragma unroll
            for (int k = 0; k < 9; k++) {
                float pnx = (float)(k / 3) - 1.f;
                float pny = (float)(k % 3) - 1.f;
                float z   = a[18 + (k % 3)] + __ldg(&b_ad[k % 3]);
                float sig = 1.f / (1.f + expf(-z));
                float ad  = 2.f * (1.f - sig);
                float px = (float)(h + 1) + pnx + a[k]     + __ldg(&b_p[k])     + ad * pnx;
                float py = (float)(w + 1) + pny + a[9 + k] + __ldg(&b_p[9 + k]) + ad * pny;
                float fx = floorf(px), fy = floorf(py);
                int iltx = (int)fx, ilty = (int)fy;
                int ltx = min(max(iltx,     0), HP - 1), lty = min(max(ilty,     0), HP - 1);
                int rbx = min(max(iltx + 1, 0), HP - 1), rby = min(max(ilty + 1, 0), HP - 1);
                bool mx = (px < 1.f) || (px > (float)(HP - 2));
                bool my = (py < 1.f) || (py > (float)(HP - 2));
                if (mx) px = fx;
                if (my) py = fy;
                px = fminf(fmaxf(px, 0.f), (float)(HP - 1));
                py = fminf(fmaxf(py, 0.f), (float)(HP - 1));
                float dxl = 1.f + ((float)ltx - px);
                float dyl = 1.f + ((float)lty - py);
                float dxr = 1.f - ((float)rbx - px);
                float dyr = 1.f - ((float)rby - py);
                g_qpack[k*MPIX + m] = (unsigned)ltx | ((unsigned)lty << 8)
                                    | ((unsigned)rbx << 16) | ((unsigned)rby << 24);
                g_w4[k*MPIX + m] = make_float4(dxl*dyl, dxr*dyr, dxl*dyr, dxr*dyl);
            }
        }
    }
}

// ================= Kernel 2: bilinear gather (NHWC) -> bf16 split X =================
// One warp per (m,k); register-packed triples, direct STG (no smem staging).
__global__ void __launch_bounds__(256) sample_kernel()
{
    const int tid  = threadIdx.x;
    const int wid  = tid >> 5, lane = tid & 31;
    const int pid  = blockIdx.x * 8 + wid;
    const int k    = pid / MPIX;
    const int m    = pid % MPIX;

    const unsigned qp = g_qpack[k*MPIX + m];
    const float4 g = g_w4[k*MPIX + m];
    const int ltx = qp & 255, lty = (qp >> 8) & 255, rbx = (qp >> 16) & 255, rby = (qp >> 24) & 255;
    const bool ax  = (ltx >= 1) && (ltx <= 96);
    const bool axr = (rbx >= 1) && (rbx <= 96);
    const bool ay  = (lty >= 1) && (lty <= 96);
    const bool ayr = (rby >= 1) && (rby <= 96);
    const float glt = (ax  && ay ) ? g.x : 0.f;
    const float grb = (axr && ayr) ? g.y : 0.f;
    const float glb = (ax  && ayr) ? g.z : 0.f;
    const float grt = (axr && ay ) ? g.w : 0.f;
    const int b = m / HW;
    const size_t base = (size_t)b * HW * C;
    const size_t oLT = (ax  && ay ) ? base + (size_t)((ltx-1)*W + (lty-1)) * C : base;
    const size_t oRB = (axr && ayr) ? base + (size_t)((rbx-1)*W + (rby-1)) * C : base;
    const size_t oLB = (ax  && ayr) ? base + (size_t)((ltx-1)*W + (rby-1)) * C : base;
    const size_t oRT = (axr && ay ) ? base + (size_t)((rbx-1)*W + (lty-1)) * C : base;

    const int c0 = lane * 8;
    float4 vLT0 = *(const float4*)&g_xT[oLT + c0];
    float4 vLT1 = *(const float4*)&g_xT[oLT + c0 + 4];
    float4 vRB0 = *(const float4*)&g_xT[oRB + c0];
    float4 vRB1 = *(const float4*)&g_xT[oRB + c0 + 4];
    float4 vLB0 = *(const float4*)&g_xT[oLB + c0];
    float4 vLB1 = *(const float4*)&g_xT[oLB + c0 + 4];
    float4 vRT0 = *(const float4*)&g_xT[oRT + c0];
    float4 vRT1 = *(const float4*)&g_xT[oRT + c0 + 4];

    float v[8];
    v[0] = glt*vLT0.x + grb*vRB0.x + glb*vLB0.x + grt*vRT0.x;
    v[1] = glt*vLT0.y + grb*vRB0.y + glb*vLB0.y + grt*vRT0.y;
    v[2] = glt*vLT0.z + grb*vRB0.z + glb*vLB0.z + grt*vRT0.z;
    v[3] = glt*vLT0.w + grb*vRB0.w + glb*vLB0.w + grt*vRT0.w;
    v[4] = glt*vLT1.x + grb*vRB1.x + glb*vLB1.x + grt*vRT1.x;
    v[5] = glt*vLT1.y + grb*vRB1.y + glb*vLB1.y + grt*vRT1.y;
    v[6] = glt*vLT1.z + grb*vRB1.z + glb*vLB1.z + grt*vRT1.z;
    v[7] = glt*vLT1.w + grb*vRB1.w + glb*vLB1.w + grt*vRT1.w;

    // pack (hi, lo, hi) triples for 8 channels -> 12 words -> 3 STG.128
    uint32_t u[12];
#pragma unroll
    for (int j = 0; j < 4; j++) {
        float f0 = v[2*j], f1 = v[2*j + 1];
        __nv_bfloat16 h0b = __float2bfloat16(f0);
        __nv_bfloat16 h1b = __float2bfloat16(f1);
        float h0f = __bfloat162float(h0b), h1f = __bfloat162float(h1b);
        __nv_bfloat16 l0b = __float2bfloat16(f0 - h0f);
        __nv_bfloat16 l1b = __float2bfloat16(f1 - h1f);
        uint32_t H0 = *reinterpret_cast<unsigned short*>(&h0b);
        uint32_t H1 = *reinterpret_cast<unsigned short*>(&h1b);
        uint32_t L0 = *reinterpret_cast<unsigned short*>(&l0b);
        uint32_t L1 = *reinterpret_cast<unsigned short*>(&l1b);
        u[3*j]     = H0 | (L0 << 16);
        u[3*j + 1] = H0 | (H1 << 16);
        u[3*j + 2] = L1 | (H1 << 16);
    }
    uint32_t* d32 = (uint32_t*)&g_Xb[(size_t)m * KD3 + (size_t)3 * k * C] + lane * 12;
    *(uint4*)(d32)     = make_uint4(u[0], u[1], u[2],  u[3]);
    *(uint4*)(d32 + 4) = make_uint4(u[4], u[5], u[6],  u[7]);
    *(uint4*)(d32 + 8) = make_uint4(u[8], u[9], u[10], u[11]);
}

// ================= Kernel 3: HMMA GEMM, CTA 128m x 256o, 512 threads =================
#define GBK 64
#define GNKIT (KD3 / GBK)        // 108
#define GNST 3
#define GA_BYTES (128 * 128)     // 16KB
#define GB_BYTES (256 * 128)     // 32KB
#define GSTG (GA_BYTES + GB_BYTES)
#define GEMM_SMEM (GNST * GSTG)  // 144KB

__device__ __forceinline__ void load_stage_g(uint32_t abase, const char* Ag, const char* Bg,
                                             int t, int tid)
{
    const size_t pitch = (size_t)KD3 * 2;      // 13824 B
    const size_t koff = (size_t)t * 128;       // 64 bf16
#pragma unroll
    for (int j = 0; j < 2; j++) {              // A: 1024 x 16B
        int idx = tid + j * 512;
        int r = idx >> 3, cc = idx & 7;
        uint32_t off = (uint32_t)(r * 128 + cc * 16);
        uint32_t sw = off ^ ((off >> 3) & 0x70);
        cp16(abase + sw, Ag + (size_t)r * pitch + koff + cc * 16);
    }
#pragma unroll
    for (int j = 0; j < 4; j++) {              // B: 2048 x 16B
        int idx = tid + j * 512;
        int r = idx >> 3, cc = idx & 7;
        uint32_t off = (uint32_t)(r * 128 + cc * 16);
        uint32_t sw = off ^ ((off >> 3) & 0x70);
        cp16(abase + GA_BYTES + sw, Bg + (size_t)r * pitch + koff + cc * 16);
    }
    cp_commit();
}

__global__ void __launch_bounds__(512, 1) mma_kernel(float* __restrict__ out)
{
    extern __shared__ char smem[];
    const uint32_t sb = smem_u32(smem);
    const int tid = threadIdx.x;
    const int wid = tid >> 5, lane = tid & 31;
    const int m0 = blockIdx.x * 128;

    const char* Ag = (const char*)&g_Xb[(size_t)m0 * KD3];
    const char* Bg = (const char*)&g_Wb[0];

    const int wm = (wid >> 2) * 32;   // 4 m-groups of 32
    const int wn = (wid & 3) * 64;    // 4 n-groups of 64

    float acc[2][8][4];
#pragma unroll
    for (int mi = 0; mi < 2; mi++)
#pragma unroll
        for (int ni = 0; ni < 8; ni++)
#pragma unroll
            for (int r = 0; r < 4; r++) acc[mi][ni][r] = 0.f;

    const int a_row = wm + (lane & 15);
    const int a_cb  = (lane >> 4) * 16;
    const int b_row = wn + (lane & 7) + ((lane >> 4) << 3);
    const int b_cb  = ((lane >> 3) & 1) * 16;

    load_stage_g(sb,        Ag, Bg, 0, tid);
    load_stage_g(sb + GSTG, Ag, Bg, 1, tid);

#pragma unroll 1
    for (int t = 0; t < GNKIT; t++) {
        if (t + 1 < GNKIT) cp_wait<1>(); else cp_wait<0>();
        __syncthreads();
        const uint32_t abase = sb + (t % GNST) * GSTG;
        const uint32_t bbase = abase + GA_BYTES;
#pragma unroll
        for (int kk = 0; kk < 4; kk++) {
            const int kb = kk * 32;
            uint32_t a[2][4], bfr[4][4];
#pragma unroll
            for (int mi = 0; mi < 2; mi++) {
                uint32_t off = (uint32_t)((a_row + mi * 16) * 128 + kb + a_cb);
                ldsm_x4(a[mi], abase + (off ^ ((off >> 3) & 0x70)));
            }
#pragma unroll
            for (int nb = 0; nb < 4; nb++) {
                uint32_t off = (uint32_t)((b_row + nb * 16) * 128 + kb + b_cb);
                ldsm_x4(bfr[nb], bbase + (off ^ ((off >> 3) & 0x70)));
            }
#pragma unroll
            for (int mi = 0; mi < 2; mi++)
#pragma unroll
                for (int ni = 0; ni < 8; ni++)
                    mma16816(acc[mi][ni], a[mi], &bfr[ni >> 1][(ni & 1) * 2]);
        }
        int u = t + 2;
        if (u < GNKIT) load_stage_g(sb + (u % GNST) * GSTG, Ag, Bg, u, tid);
    }

    // ---- epilogue: smem transpose to [o][m], coalesced stores ----
    __syncthreads();
    float* eb = (float*)smem;                 // 256 x 132 floats = 135KB (fits 144KB)
    const int er = lane >> 2;
    const int ec = (lane & 3) * 2;
#pragma unroll
    for (int mi = 0; mi < 2; mi++) {
#pragma unroll
        for (int ni = 0; ni < 8; ni++) {
            int m = wm + mi * 16 + er;
            int o = wn + ni * 8 + ec;
            eb[(o    ) * 132 + m    ] = acc[mi][ni][0];
            eb[(o + 1) * 132 + m    ] = acc[mi][ni][1];
            eb[(o    ) * 132 + m + 8] = acc[mi][ni][2];
            eb[(o + 1) * 132 + m + 8] = acc[mi][ni][3];
        }
    }
    __syncthreads();
    const int b   = m0 / HW;
    const int hw0 = m0 % HW;
#pragma unroll
    for (int i = 0; i < 16; i++) {
        int idx = tid + i * 512;
        int r = idx >> 5, c4 = (idx & 31) * 4;
        float4 v = *(const float4*)&eb[r * 132 + c4];
        *(float4*)&out[(size_t)(b * OC + r) * HW + hw0 + c4] = v;
    }
}

// ================= launch =================
extern "C" void kernel_launch(void* const* d_in, const int* in_sizes, int n_in,
                              void* d_out, int out_size)
{
    const float* x      = (const float*)d_in[0];
    const float* w_p    = (const float*)d_in[1];
    const float* b_p    = (const float*)d_in[2];
    const float* w_ad   = (const float*)d_in[3];
    const float* b_ad   = (const float*)d_in[4];
    const float* w_conv = (const float*)d_in[5];
    float* out = (float*)d_out;

    cudaFuncSetAttribute(mma_kernel, cudaFuncAttributeMaxDynamicSharedMemorySize, GEMM_SMEM);

    wt_kernel<<<OC, C>>>(w_conv);
    tr_kernel<<<dim3(HW / 32, C / 32, BDIM), 256>>>(x);
    offset_kernel<<<MPIX / 128, 256>>>(x, w_p, b_p, w_ad, b_ad);
    sample_kernel<<<MPIX * NTAP / 8, 256>>>();
    mma_kernel<<<MPIX / 128, 512, GEMM_SMEM>>>(out);
}